// round 9
// baseline (speedup 1.0000x reference)
#include <cuda_runtime.h>

// AudioDeviceModel_89008902242543  — R8
//
// s[b]      = dot(x[b,:], w1[0,:,0]) + b1+b2+b3+b4+b5
// out[b,d]  = s[b]*wd[d] + bd[d]            (B=8192, L=16384, D=128)
//
// HBM-read-bound (512 MB of x). RPB axis optimum found at RPB=2 (R6:
// 86.6% DRAM); RPB=1 regressed steady-state (R7). R8 keeps R6's inner
// loop but goes PERSISTENT: exactly one resident wave (148 SMs x occ4
// = 592 CTAs) grid-striding over 4096 row-groups. Removes the ~7
// discrete wave transitions + ragged refill; imbalance ~1.2%.

#define B_ROWS  8192
#define L_COLS  16384
#define L4      (L_COLS / 4)   // 4096 float4 per row
#define RPB     2              // rows per group
#define NGROUPS (B_ROWS / RPB) // 4096
#define NT      256            // threads per block
#define NWARPS  (NT / 32)
#define UNR     4              // column steps per batch
#define ITERS   (L4 / NT)      // 16 -> 4 batches of UNR
#define NCTAS   592            // 148 SMs x 4 CTAs/SM = one resident wave

__device__ __forceinline__ float dot4_acc(float4 xx, float4 w, float a) {
    return fmaf(xx.x, w.x, fmaf(xx.y, w.y, fmaf(xx.z, w.z, fmaf(xx.w, w.w, a))));
}

__global__ __launch_bounds__(NT, 4)
void audio_model_kernel(const float* __restrict__ x,
                        const float* __restrict__ w1,
                        const float* __restrict__ b1,
                        const float* __restrict__ b2,
                        const float* __restrict__ b3,
                        const float* __restrict__ b4,
                        const float* __restrict__ b5,
                        const float* __restrict__ wd,
                        const float* __restrict__ bd,
                        float* __restrict__ out)
{
    const int tid = threadIdx.x;
    const int wid = tid >> 5;
    const int lid = tid & 31;

    const float4* __restrict__ wv = reinterpret_cast<const float4*>(w1);
    const float4* __restrict__ xbase = reinterpret_cast<const float4*>(x);

    __shared__ float part[NWARPS][RPB];
    __shared__ float srow[RPB];

    const float bias = b1[0] + b2[0] + b3[0] + b4[0] + b5[0];

    // Persistent grid-stride over row-groups: one resident wave, no
    // wave-transition bubbles; per-CTA imbalance <= 1 group (~1.2%).
#pragma unroll 1
    for (int g = blockIdx.x; g < NGROUPS; g += NCTAS) {
        const int b0 = g * RPB;
        const float4* __restrict__ xv = xbase + (size_t)b0 * L4;

        float acc[RPB];
#pragma unroll
        for (int r = 0; r < RPB; r++) acc[r] = 0.0f;

        int i = tid;
#pragma unroll 1
        for (int it = 0; it < ITERS; it += UNR, i += UNR * NT) {
            // Front-batch the 8 HBM loads (2 rows x 4 column steps).
            float4 xx[RPB][UNR];
#pragma unroll
            for (int u = 0; u < UNR; u++)
#pragma unroll
                for (int r = 0; r < RPB; r++)
                    xx[r][u] = __ldcs(&xv[(size_t)r * L4 + i + u * NT]);

            // w loads are L2 hits; JIT to save registers.
#pragma unroll
            for (int u = 0; u < UNR; u++) {
                float4 w = wv[i + u * NT];
#pragma unroll
                for (int r = 0; r < RPB; r++)
                    acc[r] = dot4_acc(xx[r][u], w, acc[r]);
            }
        }

        // Intra-warp tree reduction for each row accumulator.
#pragma unroll
        for (int r = 0; r < RPB; r++) {
#pragma unroll
            for (int off = 16; off > 0; off >>= 1)
                acc[r] += __shfl_xor_sync(0xffffffffu, acc[r], off);
        }

        if (lid == 0) {
#pragma unroll
            for (int r = 0; r < RPB; r++) part[wid][r] = acc[r];
        }
        __syncthreads();

        if (tid < RPB) {
            float s = 0.0f;
#pragma unroll
            for (int w = 0; w < NWARPS; w++) s += part[w][tid];
            srow[tid] = s + bias;
        }
        __syncthreads();

        // Epilogue: 2 rows x 128 outputs, coalesced.
#pragma unroll
        for (int j = tid; j < RPB * 128; j += NT) {
            const int r = j >> 7;
            const int d = j & 127;
            out[(size_t)(b0 + r) * 128 + d] = fmaf(srow[r], wd[d], bd[d]);
        }
        __syncthreads();   // protect srow/part before next group's writes
    }
}

extern "C" void kernel_launch(void* const* d_in, const int* in_sizes, int n_in,
                              void* d_out, int out_size)
{
    // metadata order: x, w1, b1, w2, b2, w3, b3, w4, b4, w5, b5, wd, bd
    const float* x  = (const float*)d_in[0];
    const float* w1 = (const float*)d_in[1];
    const float* b1 = (const float*)d_in[2];
    const float* b2 = (const float*)d_in[4];
    const float* b3 = (const float*)d_in[6];
    const float* b4 = (const float*)d_in[8];
    const float* b5 = (const float*)d_in[10];
    const float* wd = (const float*)d_in[11];
    const float* bd = (const float*)d_in[12];
    float* out = (float*)d_out;

    audio_model_kernel<<<NCTAS, NT>>>(x, w1, b1, b2, b3, b4, b5, wd, bd, out);
}